// round 17
// baseline (speedup 1.0000x reference)
#include <cuda_runtime.h>
#include <cuda_fp16.h>
#include <cstdint>
#include <math.h>

// ---------------- problem constants ----------------
#define D_MODEL 1024
#define HEADS   8
#define DH      128
#define DEPTH   2
#define BATCH   2
#define TOKENS  2048
#define GRP     128
#define NGRP    16
#define SEQ     2064
#define MROWS   (BATCH*SEQ)    // 4128
#define DFF     4096

// ---------------- fp32 scratch ----------------
#define OFF_XS    0L
#define SZ_XS     ((long)MROWS*D_MODEL)
#define OFF_RPRJ  (OFF_XS + SZ_XS)
#define SZ_RPRJ   (32L*D_MODEL)
#define SCRATCH_FLOATS (OFF_RPRJ + SZ_RPRJ)

__device__ float g_scratch[SCRATCH_FLOATS];

// ---------------- fp16 scratch (offsets in halves) ----------------
// weights stored per-tensor, contiguous across layers
#define SZ_RQKV_ALL ((long)DEPTH*D_MODEL*3*D_MODEL)
#define SZ_ROW_ALL  ((long)DEPTH*D_MODEL*D_MODEL)
#define SZ_FW1_ALL  ((long)DEPTH*D_MODEL*DFF)
#define HW_RQKV   0L
#define HW_ROW    (HW_RQKV + SZ_RQKV_ALL)
#define HW_LQKV   (HW_ROW + SZ_ROW_ALL)
#define HW_LOW    (HW_LQKV + SZ_RQKV_ALL)
#define HW_FW1    (HW_LOW + SZ_ROW_ALL)
#define HW_FW2    (HW_FW1 + SZ_FW1_ALL)
#define HOFF_Y    (HW_FW2 + SZ_FW1_ALL)
#define SZ_HY     ((long)MROWS*D_MODEL)
#define HOFF_QKV  (HOFF_Y + SZ_HY)
#define SZ_HQKV   ((long)MROWS*3*D_MODEL)
#define HOFF_ATT  (HOFF_QKV + SZ_HQKV)
#define SZ_HATT   ((long)MROWS*D_MODEL)
#define HOFF_FFN  (HOFF_ATT + SZ_HATT)
#define SZ_HFFN   ((long)MROWS*DFF)
#define HOFF_RLN  (HOFF_FFN + SZ_HFFN)
#define SZ_HRLN   (32L*D_MODEL)
#define HOFF_RQKV (HOFF_RLN + SZ_HRLN)
#define SZ_HRQKV  (32L*3*D_MODEL)
#define HOFF_RATT (HOFF_RQKV + SZ_HRQKV)
#define SZ_HRATT  (32L*D_MODEL)
#define HSCRATCH_HALVES (HOFF_RATT + SZ_HRATT)

__device__ __align__(16) __half g_hscratch[HSCRATCH_HALVES];

// ---------------- helpers ----------------
__device__ __forceinline__ uint32_t smem_u32(const void* p) {
    uint32_t a;
    asm("{ .reg .u64 t; cvta.to.shared.u64 t, %1; cvt.u32.u64 %0, t; }" : "=r"(a) : "l"(p));
    return a;
}

__device__ __forceinline__ uint32_t pack_h2(float lo, float hi) {
    __half2 h = __floats2half2_rn(lo, hi);   // low 16 bits = lo
    return *reinterpret_cast<uint32_t*>(&h);
}

__device__ __forceinline__ void mma_f16(float& d0, float& d1, float& d2, float& d3,
                                        uint32_t a0, uint32_t a1, uint32_t a2, uint32_t a3,
                                        uint32_t b0, uint32_t b1)
{
    asm volatile("mma.sync.aligned.m16n8k16.row.col.f32.f16.f16.f32 "
                 "{%0,%1,%2,%3}, {%4,%5,%6,%7}, {%8,%9}, {%0,%1,%2,%3};\n"
                 : "+f"(d0), "+f"(d1), "+f"(d2), "+f"(d3)
                 : "r"(a0), "r"(a1), "r"(a2), "r"(a3), "r"(b0), "r"(b1));
}

__device__ __forceinline__ void ldsm_x4(uint32_t& r0, uint32_t& r1,
                                        uint32_t& r2, uint32_t& r3, uint32_t addr)
{
    asm volatile("ldmatrix.sync.aligned.m8n8.x4.shared.b16 {%0,%1,%2,%3}, [%4];"
                 : "=r"(r0), "=r"(r1), "=r"(r2), "=r"(r3) : "r"(addr));
}

__device__ __forceinline__ void ldsm_x4_trans(uint32_t& r0, uint32_t& r1,
                                              uint32_t& r2, uint32_t& r3, uint32_t addr)
{
    asm volatile("ldmatrix.sync.aligned.m8n8.x4.trans.shared.b16 {%0,%1,%2,%3}, [%4];"
                 : "=r"(r0), "=r"(r1), "=r"(r2), "=r"(r3) : "r"(addr));
}

// ---------------- fp32 -> fp16 conversion (whole tensors) ----------------
__global__ __launch_bounds__(256)
void cvt_h(const float* __restrict__ src, long dst_off, long n)
{
    __half* __restrict__ dst = g_hscratch + dst_off;
    long i = ((long)blockIdx.x * 256 + threadIdx.x) * 8;
    if (i >= n) return;
    float4 a = *reinterpret_cast<const float4*>(src + i);
    float4 b = *reinterpret_cast<const float4*>(src + i + 4);
    uint4 u = make_uint4(pack_h2(a.x, a.y), pack_h2(a.z, a.w),
                         pack_h2(b.x, b.y), pack_h2(b.z, b.w));
    *reinterpret_cast<uint4*>(dst + i) = u;
}

// ================= fp16 mma GEMM, warp tile 64x64 =================
// C = A(MxK) @ B(KxN); A,B fp16 (g_hscratch offsets), C fp32 (g_scratch) or fp16 (bit 8).
// EP bits: 1=+bias(f32), 2=residual-accumulate(f32 C), 4=leaky_relu, 8=fp16 output
// Block 128x128, BK=32, 4 warps (2x2), warp tile 64x64, m16n8k16.
template<int EP>
__global__ __launch_bounds__(128)
void gemm_h16(long a_off, long b_off, const float* __restrict__ bias, long c_off,
              int M, int N, int K)
{
    __shared__ __align__(16) uint32_t As[2][128 * 20];   // [m][16 data + 4 pad] half2 words
    __shared__ __align__(16) uint32_t Bs[2][32 * 68];    // [k][64 data + 4 pad] half2 words

    const __half* __restrict__ A = g_hscratch + a_off;
    const __half* __restrict__ B = g_hscratch + b_off;

    const int tid = threadIdx.x;
    const int lane = tid & 31;
    const int wid = tid >> 5;
    const int warp_m = wid >> 1;        // 0..1
    const int warp_n = wid & 1;         // 0..1
    const int g  = lane >> 2;
    const int tg = lane & 3;
    const int bm = blockIdx.y * 128;
    const int bn = blockIdx.x * 128;

    const uint32_t bsA = smem_u32(&As[0][0]);
    const uint32_t bsB = smem_u32(&Bs[0][0]);

    // ldmatrix.x4 A lane mapping (validated R14)
    const int a_rowoff = ((lane >> 3) & 1) * 8 + (lane & 7);
    const int a_kword  = (lane >> 4) * 4;

    // staging indices: A 512 uint4, B 512 uint4; 4 each per thread (128 threads)
    int a_r[4], a_q[4], a_gr[4], b_r[4], b_q[4];
    #pragma unroll
    for (int i = 0; i < 4; i++) {
        int idx = tid + i * 128;
        a_r[i] = idx >> 2;  a_q[i] = idx & 3;
        b_r[i] = idx >> 4;  b_q[i] = idx & 15;
        int r = bm + a_r[i];
        a_gr[i] = (r < M) ? r : (M - 1);
    }

    float acc[4][8][4];
    #pragma unroll
    for (int mi = 0; mi < 4; mi++)
        #pragma unroll
        for (int ni = 0; ni < 8; ni++)
            #pragma unroll
            for (int q = 0; q < 4; q++) acc[mi][ni][q] = 0.f;

    const int nk = K / 32;
    uint4 aR[4], bR[4];

    #pragma unroll
    for (int i = 0; i < 4; i++) {
        aR[i] = *reinterpret_cast<const uint4*>(A + (size_t)a_gr[i] * K + a_q[i] * 8);
        bR[i] = *reinterpret_cast<const uint4*>(B + (size_t)b_r[i] * N + bn + b_q[i] * 8);
    }
    #pragma unroll
    for (int i = 0; i < 4; i++) {
        *reinterpret_cast<uint4*>(&As[0][a_r[i] * 20 + a_q[i] * 4]) = aR[i];
        *reinterpret_cast<uint4*>(&Bs[0][b_r[i] * 68 + b_q[i] * 4]) = bR[i];
    }
    __syncthreads();

    for (int s = 0; s < nk; s++) {
        const int cur = s & 1;
        if (s + 1 < nk) {
            const int k0 = (s + 1) * 32;
            #pragma unroll
            for (int i = 0; i < 4; i++) {
                aR[i] = *reinterpret_cast<const uint4*>(A + (size_t)a_gr[i] * K + k0 + a_q[i] * 8);
                bR[i] = *reinterpret_cast<const uint4*>(B + (size_t)(k0 + b_r[i]) * N + bn + b_q[i] * 8);
            }
        }

        const uint32_t abase = bsA + (uint32_t)cur * (128 * 20 * 4);
        const uint32_t bbase = bsB + (uint32_t)cur * (32 * 68 * 4);
        #pragma unroll
        for (int ks = 0; ks < 2; ks++) {
            uint32_t bf[8][2];
            #pragma unroll
            for (int nip = 0; nip < 4; nip++) {
                const int krow = ks * 16 + (lane & 15);
                const int ncol = warp_n * 64 + nip * 16 + ((lane & 16) ? 8 : 0);
                const uint32_t addr = bbase + (uint32_t)(krow * 68 + (ncol >> 1)) * 4;
                ldsm_x4_trans(bf[nip*2][0], bf[nip*2][1], bf[nip*2+1][0], bf[nip*2+1][1], addr);
            }
            #pragma unroll
            for (int mi = 0; mi < 4; mi++) {
                const int r = warp_m * 64 + mi * 16 + a_rowoff;
                const uint32_t aaddr = abase + (uint32_t)(r * 20 + ks * 8 + a_kword) * 4;
                uint32_t a0, a1, a2, a3;
                ldsm_x4(a0, a1, a2, a3, aaddr);
                #pragma unroll
                for (int ni = 0; ni < 8; ni++)
                    mma_f16(acc[mi][ni][0], acc[mi][ni][1], acc[mi][ni][2], acc[mi][ni][3],
                            a0, a1, a2, a3, bf[ni][0], bf[ni][1]);
            }
        }

        if (s + 1 < nk) {
            const int nxt = (s + 1) & 1;
            #pragma unroll
            for (int i = 0; i < 4; i++) {
                *reinterpret_cast<uint4*>(&As[nxt][a_r[i] * 20 + a_q[i] * 4]) = aR[i];
                *reinterpret_cast<uint4*>(&Bs[nxt][b_r[i] * 68 + b_q[i] * 4]) = bR[i];
            }
        }
        __syncthreads();
    }

    // epilogue
    #pragma unroll
    for (int mi = 0; mi < 4; mi++) {
        #pragma unroll
        for (int half = 0; half < 2; half++) {
            const int r = bm + warp_m * 64 + mi * 16 + g + half * 8;
            if (r >= M) continue;
            #pragma unroll
            for (int ni = 0; ni < 8; ni++) {
                float v0 = acc[mi][ni][half * 2 + 0];
                float v1 = acc[mi][ni][half * 2 + 1];
                const int c = bn + warp_n * 64 + ni * 8 + tg * 2;
                if (EP & 1) { v0 += bias[c]; v1 += bias[c + 1]; }
                if (EP & 4) {
                    v0 = v0 > 0.f ? v0 : 0.01f * v0;
                    v1 = v1 > 0.f ? v1 : 0.01f * v1;
                }
                if (EP & 8) {
                    __half* cp = g_hscratch + c_off + (size_t)r * N + c;
                    *reinterpret_cast<uint32_t*>(cp) = pack_h2(v0, v1);
                } else {
                    float* cp = g_scratch + c_off + (size_t)r * N + c;
                    if (EP & 2) {
                        float2 old = *reinterpret_cast<float2*>(cp);
                        v0 += old.x; v1 += old.y;
                    }
                    *reinterpret_cast<float2*>(cp) = make_float2(v0, v1);
                }
            }
        }
    }
}

// ---------------- LayerNorm: fp32 in (strided), fp16 out [row][1024] ----------------
__global__ __launch_bounds__(256)
void ln_kernel(long in_off, long out_off_h,
               const float* __restrict__ gamma, const float* __restrict__ beta,
               long in_stride)
{
    const float* __restrict__ in = g_scratch + in_off;
    __half* __restrict__ out = g_hscratch + out_off_h;

    const int row = blockIdx.x;
    const int tid = threadIdx.x;
    const float4 v = reinterpret_cast<const float4*>(in + (size_t)row * in_stride)[tid];

    float s  = v.x + v.y + v.z + v.w;
    float sq = v.x*v.x + v.y*v.y + v.z*v.z + v.w*v.w;
    #pragma unroll
    for (int o = 16; o > 0; o >>= 1) {
        s  += __shfl_xor_sync(0xffffffffu, s,  o);
        sq += __shfl_xor_sync(0xffffffffu, sq, o);
    }
    __shared__ float ss[8], sqs[8];
    const int warp = tid >> 5;
    if ((tid & 31) == 0) { ss[warp] = s; sqs[warp] = sq; }
    __syncthreads();
    float ts = 0.f, tq = 0.f;
    #pragma unroll
    for (int w = 0; w < 8; w++) { ts += ss[w]; tq += sqs[w]; }
    const float mean = ts * (1.0f / D_MODEL);
    const float var  = tq * (1.0f / D_MODEL) - mean * mean;
    const float rstd = rsqrtf(var + 1e-5f);

    const float4 g4 = reinterpret_cast<const float4*>(gamma)[tid];
    const float4 b4 = reinterpret_cast<const float4*>(beta)[tid];
    float o0 = (v.x - mean) * rstd * g4.x + b4.x;
    float o1 = (v.y - mean) * rstd * g4.y + b4.y;
    float o2 = (v.z - mean) * rstd * g4.z + b4.z;
    float o3 = (v.w - mean) * rstd * g4.w + b4.w;
    *reinterpret_cast<uint2*>(out + (size_t)row * D_MODEL + tid * 4) =
        make_uint2(pack_h2(o0, o1), pack_h2(o2, o3));
}

// ---------------- fp16 flash attention (unscaled dots!), fp16 in/out ----------------
// Br=64, Bc=64, 4 warps. K B-frags via ldmatrix.x4 (non-trans); V via ldmatrix.x4.trans.
__global__ __launch_bounds__(128)
void flash_attn_f16(long qkv_off, long out_off, int S)
{
    __shared__ __align__(16) uint32_t KS[64 * 68];
    __shared__ __align__(16) uint32_t VS[64 * 68];

    const __half* __restrict__ qkv = g_hscratch + qkv_off;
    __half* __restrict__ out = g_hscratch + out_off;

    const int b = blockIdx.z, h = blockIdx.y;
    const int q0 = blockIdx.x * 64;
    const int tid = threadIdx.x;
    const int lane = tid & 31, wid = tid >> 5;
    const int g = lane >> 2, tg = lane & 3;
    const __half* base = qkv + (size_t)b * S * (3 * D_MODEL);
    const uint32_t ksb = smem_u32(&KS[0]);
    const uint32_t vsb = smem_u32(&VS[0]);

    // ldsm lane mapping for K B-frags: mat0/1 = octet pair lo, words +0/+4; mat2/3 = next octet
    const int k_rowoff = (lane & 7) + ((lane >> 4) & 1) * 8;
    const int k_wordoff = ((lane >> 3) & 1) * 4;

    // ---- stage Q into KS, lift to A-frags ----
    #pragma unroll
    for (int it = 0; it < 8; it++) {
        int idx = it * 128 + tid;
        int r = idx >> 4, q = idx & 15;
        int qr = q0 + r; if (qr >= S) qr = S - 1;
        uint4 v = *reinterpret_cast<const uint4*>(base + (size_t)qr * (3*D_MODEL) + h * DH + q * 8);
        *reinterpret_cast<uint4*>(&KS[r * 68 + q * 4]) = v;
    }
    __syncthreads();
    uint32_t qf[8][4];
    {
        const int qrow = wid * 16 + g;
        #pragma unroll
        for (int c = 0; c < 8; c++) {
            qf[c][0] = KS[qrow * 68 + c * 8 + tg];
            qf[c][1] = KS[(qrow + 8) * 68 + c * 8 + tg];
            qf[c][2] = KS[qrow * 68 + c * 8 + tg + 4];
            qf[c][3] = KS[(qrow + 8) * 68 + c * 8 + tg + 4];
        }
    }

    float o_acc[16][4];
    #pragma unroll
    for (int ni = 0; ni < 16; ni++)
        o_acc[ni][0] = o_acc[ni][1] = o_acc[ni][2] = o_acc[ni][3] = 0.f;
    float m0 = -1e30f, m1 = -1e30f, l0 = 0.f, l1 = 0.f;

    for (int kt = 0; kt < S; kt += 64) {
        __syncthreads();
        // stage K and V together
        #pragma unroll
        for (int it = 0; it < 8; it++) {
            int idx = it * 128 + tid;
            int r = idx >> 4, q = idx & 15;
            int kr = kt + r; if (kr >= S) kr = S - 1;
            const __half* rp = base + (size_t)kr * (3*D_MODEL) + h * DH + q * 8;
            uint4 vk = *reinterpret_cast<const uint4*>(rp + D_MODEL);
            uint4 vv = *reinterpret_cast<const uint4*>(rp + 2 * D_MODEL);
            *reinterpret_cast<uint4*>(&KS[r * 68 + q * 4]) = vk;
            *reinterpret_cast<uint4*>(&VS[r * 68 + q * 4]) = vv;
        }
        __syncthreads();

        // S = Q K^T : K B-frags via ldsm.x4 (2 octets per instruction)
        float sf[8][4];
        #pragma unroll
        for (int ni = 0; ni < 8; ni++)
            sf[ni][0] = sf[ni][1] = sf[ni][2] = sf[ni][3] = 0.f;
        #pragma unroll
        for (int c = 0; c < 8; c++) {
            #pragma unroll
            for (int jp = 0; jp < 4; jp++) {
                const uint32_t addr = ksb +
                    (uint32_t)((jp * 16 + k_rowoff) * 68 + c * 8 + k_wordoff) * 4;
                uint32_t b00, b01, b10, b11;
                ldsm_x4(b00, b01, b10, b11, addr);
                mma_f16(sf[jp*2][0], sf[jp*2][1], sf[jp*2][2], sf[jp*2][3],
                        qf[c][0], qf[c][1], qf[c][2], qf[c][3], b00, b01);
                mma_f16(sf[jp*2+1][0], sf[jp*2+1][1], sf[jp*2+1][2], sf[jp*2+1][3],
                        qf[c][0], qf[c][1], qf[c][2], qf[c][3], b10, b11);
            }
        }

        // online softmax
        float mx0 = -1e30f, mx1 = -1e30f;
        #pragma unroll
        for (int ni = 0; ni < 8; ni++) {
            int c = kt + ni * 8 + tg * 2;
            if (c >= S)     { sf[ni][0] = -1e30f; sf[ni][2] = -1e30f; }
            if (c + 1 >= S) { sf[ni][1] = -1e30f; sf[ni][3] = -1e30f; }
            mx0 = fmaxf(mx0, fmaxf(sf[ni][0], sf[ni][1]));
            mx1 = fmaxf(mx1, fmaxf(sf[ni][2], sf[ni][3]));
        }
        mx0 = fmaxf(mx0, __shfl_xor_sync(0xffffffffu, mx0, 1));
        mx0 = fmaxf(mx0, __shfl_xor_sync(0xffffffffu, mx0, 2));
        mx1 = fmaxf(mx1, __shfl_xor_sync(0xffffffffu, mx1, 1));
        mx1 = fmaxf(mx1, __shfl_xor_sync(0xffffffffu, mx1, 2));
        const float M0 = fmaxf(m0, mx0), M1 = fmaxf(m1, mx1);
        const float sc0 = __expf(m0 - M0), sc1 = __expf(m1 - M1);
        float rs0 = 0.f, rs1 = 0.f;
        uint32_t ph[8][2];
        #pragma unroll
        for (int ni = 0; ni < 8; ni++) {
            float p00 = __expf(sf[ni][0] - M0);
            float p01 = __expf(sf[ni][1] - M0);
            float p10 = __expf(sf[ni][2] - M1);
            float p11 = __expf(sf[ni][3] - M1);
            rs0 += p00 + p01; rs1 += p10 + p11;
            ph[ni][0] = pack_h2(p00, p01);
            ph[ni][1] = pack_h2(p10, p11);
        }
        rs0 += __shfl_xor_sync(0xffffffffu, rs0, 1);
        rs0 += __shfl_xor_sync(0xffffffffu, rs0, 2);
        rs1 += __shfl_xor_sync(0xffffffffu, rs1, 1);
        rs1 += __shfl_xor_sync(0xffffffffu, rs1, 2);
        l0 = l0 * sc0 + rs0; l1 = l1 * sc1 + rs1;
        m0 = M0; m1 = M1;
        #pragma unroll
        for (int ni = 0; ni < 16; ni++) {
            o_acc[ni][0] *= sc0; o_acc[ni][1] *= sc0;
            o_acc[ni][2] *= sc1; o_acc[ni][3] *= sc1;
        }

        // O += P V
        #pragma unroll
        for (int jc = 0; jc < 4; jc++) {
            uint32_t pa0 = ph[2*jc][0], pa1 = ph[2*jc][1];
            uint32_t pa2 = ph[2*jc+1][0], pa3 = ph[2*jc+1][1];
            #pragma unroll
            for (int nip = 0; nip < 8; nip++) {
                const int krow = jc * 16 + (lane & 15);
                const int dcol = nip * 16 + ((lane & 16) ? 8 : 0);
                const uint32_t addr = vsb + (uint32_t)(krow * 68 + (dcol >> 1)) * 4;
                uint32_t b00, b01, b10, b11;
                ldsm_x4_trans(b00, b01, b10, b11, addr);
                mma_f16(o_acc[nip*2][0], o_acc[nip*2][1], o_acc[nip*2][2], o_acc[nip*2][3],
                        pa0, pa1, pa2, pa3, b00, b01);
                mma_f16(o_acc[nip*2+1][0], o_acc[nip*2+1][1], o_acc[nip*2+1][2], o_acc[nip*2+1][3],
                        pa0, pa1, pa2, pa3, b10, b11);
            }
        }
    }

    const float inv0 = 1.f / l0, inv1 = 1.f / l1;
    const int r0 = q0 + wid * 16 + g, r1 = r0 + 8;
    #pragma unroll
    for (int ni = 0; ni < 16; ni++) {
        const int c = h * DH + ni * 8 + tg * 2;
        if (r0 < S)
            *reinterpret_cast<uint32_t*>(out + (size_t)(b * S + r0) * D_MODEL + c) =
                pack_h2(o_acc[ni][0] * inv0, o_acc[ni][1] * inv0);
        if (r1 < S)
            *reinterpret_cast<uint32_t*>(out + (size_t)(b * S + r1) * D_MODEL + c) =
                pack_h2(o_acc[ni][2] * inv1, o_acc[ni][3] * inv1);
    }
}

// ---------------- relay attention (16 tokens), fp16 in/out ----------------
__global__ __launch_bounds__(128)
void relay_attn(long rqkv_off, long ratt_off)
{
    const __half* __restrict__ rqkv = g_hscratch + rqkv_off;
    __half* __restrict__ rattn = g_hscratch + ratt_off;

    const int h = blockIdx.x, b = blockIdx.y;
    __shared__ float q[16][128], k[16][128], v[16][128];
    __shared__ float p[16][16];
    const int tid = threadIdx.x;

    #pragma unroll
    for (int it = 0; it < 2; it++) {
        int idx = it * 128 + tid;
        int r = idx >> 4, qq = idx & 15;
        const __half* rowp = rqkv + (size_t)(b * 16 + r) * (3 * D_MODEL) + h * DH + qq * 8;
        #pragma unroll
        for (int m = 0; m < 3; m++) {
            float* dst = (m == 0 ? &q[r][qq*8] : (m == 1 ? &k[r][qq*8] : &v[r][qq*8]));
            const __half* sp = rowp + m * D_MODEL;
            #pragma unroll
            for (int e = 0; e < 8; e++) dst[e] = __half2float(sp[e]);
        }
    }
    __syncthreads();

    #pragma unroll
    for (int t = 0; t < 2; t++) {
        int ij = tid * 2 + t;
        int i = ij >> 4, j = ij & 15;
        float s = 0.f;
        for (int d = 0; d < 128; d += 4) {
            float4 qa = *reinterpret_cast<float4*>(&q[i][d]);
            float4 ka = *reinterpret_cast<float4*>(&k[j][d]);
            s += qa.x*ka.x + qa.y*ka.y + qa.z*ka.z + qa.w*ka.w;
        }
        p[i][j] = s;
    }
    __syncthreads();

    if (tid < 16) {
        float mx = -1e30f;
        #pragma unroll
        for (int j = 0; j < 16; j++) mx = fmaxf(mx, p[tid][j]);
        float sum = 0.f; float e[16];
        #pragma unroll
        for (int j = 0; j < 16; j++) { e[j] = __expf(p[tid][j] - mx); sum += e[j]; }
        float inv = 1.0f / sum;
        #pragma unroll
        for (int j = 0; j < 16; j++) p[tid][j] = e[j] * inv;
    }
    __syncthreads();

    const int i = tid >> 3, c0 = (tid & 7) * 16;
    #pragma unroll
    for (int c = 0; c < 16; c += 2) {
        float o0 = 0.f, o1 = 0.f;
        #pragma unroll
        for (int j = 0; j < 16; j++) {
            o0 += p[i][j] * v[j][c0 + c];
            o1 += p[i][j] * v[j][c0 + c + 1];
        }
        *reinterpret_cast<uint32_t*>(rattn + (size_t)(b * 16 + i) * D_MODEL + h * DH + c0 + c) =
            pack_h2(o0, o1);
    }
}

// ---------------- small glue kernels ----------------
__global__ void init_xs(const float* __restrict__ x, const float* __restrict__ relay_emb)
{
    float* __restrict__ xs = g_scratch + OFF_XS;
    const int row = blockIdx.x;
    const int b = row / SEQ, sr = row % SEQ;
    const int grp = sr / (GRP + 1), w = sr % (GRP + 1);
    float4 val;
    if (w == 0)
        val = reinterpret_cast<const float4*>(relay_emb)[threadIdx.x];
    else {
        int t = grp * GRP + (w - 1);
        val = reinterpret_cast<const float4*>(x + (size_t)(b * TOKENS + t) * D_MODEL)[threadIdx.x];
    }
    reinterpret_cast<float4*>(xs + (size_t)row * D_MODEL)[threadIdx.x] = val;
}

__global__ void relay_scatter(long rprj_off, const float* __restrict__ bias)
{
    const float* __restrict__ rproj = g_scratch + rprj_off;
    float* __restrict__ xs = g_scratch + OFF_XS;
    const int row = blockIdx.x;
    float4 r = reinterpret_cast<const float4*>(rproj + (size_t)row * D_MODEL)[threadIdx.x];
    float4 bb = reinterpret_cast<const float4*>(bias)[threadIdx.x];
    float4* dst = reinterpret_cast<float4*>(xs + (size_t)row * (GRP + 1) * D_MODEL) + threadIdx.x;
    float4 c = *dst;
    c.x += r.x + bb.x; c.y += r.y + bb.y; c.z += r.z + bb.z; c.w += r.w + bb.w;
    *dst = c;
}

__global__ void final_out(float* __restrict__ out)
{
    const float* __restrict__ xs = g_scratch + OFF_XS;
    const int row = blockIdx.x;
    const int b = row / TOKENS, t = row % TOKENS;
    const int src = b * SEQ + (t >> 7) * (GRP + 1) + 1 + (t & 127);
    reinterpret_cast<float4*>(out + (size_t)row * D_MODEL)[threadIdx.x] =
        reinterpret_cast<const float4*>(xs + (size_t)src * D_MODEL)[threadIdx.x];
}

// ---------------- host side ----------------
static void launch_cvt(const float* src, long dst_off, long n)
{
    cvt_h<<<(unsigned)((n / 8 + 255) / 256), 256>>>(src, dst_off, n);
}

static void launch_gemm(int ep, long a_off, long b_off, const float* bias,
                        long c_off, int M, int N, int K)
{
    dim3 grid(N / 128, (M + 127) / 128);
    switch (ep) {
        case 0:  gemm_h16<0><<<grid, 128>>>(a_off, b_off, bias, c_off, M, N, K); break;
        case 3:  gemm_h16<3><<<grid, 128>>>(a_off, b_off, bias, c_off, M, N, K); break;
        case 8:  gemm_h16<8><<<grid, 128>>>(a_off, b_off, bias, c_off, M, N, K); break;
        case 13: gemm_h16<13><<<grid, 128>>>(a_off, b_off, bias, c_off, M, N, K); break;
    }
}

extern "C" void kernel_launch(void* const* d_in, const int* in_sizes, int n_in,
                              void* d_out, int out_size)
{
    const float* x         = (const float*)d_in[0];
    const float* relay_emb = (const float*)d_in[1];
    const float* r_ln_g    = (const float*)d_in[2];
    const float* r_ln_b    = (const float*)d_in[3];
    const float* r_qkv     = (const float*)d_in[4];
    const float* r_ow      = (const float*)d_in[5];
    const float* r_ob      = (const float*)d_in[6];
    const float* l_ln_g    = (const float*)d_in[7];
    const float* l_ln_b    = (const float*)d_in[8];
    const float* l_qkv     = (const float*)d_in[9];
    const float* l_ow      = (const float*)d_in[10];
    const float* l_ob      = (const float*)d_in[11];
    const float* f_ln_g    = (const float*)d_in[12];
    const float* f_ln_b    = (const float*)d_in[13];
    const float* f_w1      = (const float*)d_in[14];
    const float* f_b1      = (const float*)d_in[15];
    const float* f_w2      = (const float*)d_in[16];
    const float* f_b2      = (const float*)d_in[17];

    // one-time weight conversion: whole tensors (contiguous across layers)
    launch_cvt(r_qkv, HW_RQKV, SZ_RQKV_ALL);
    launch_cvt(r_ow,  HW_ROW,  SZ_ROW_ALL);
    launch_cvt(l_qkv, HW_LQKV, SZ_RQKV_ALL);
    launch_cvt(l_ow,  HW_LOW,  SZ_ROW_ALL);
    launch_cvt(f_w1,  HW_FW1,  SZ_FW1_ALL);
    launch_cvt(f_w2,  HW_FW2,  SZ_FW1_ALL);

    init_xs<<<MROWS, 256>>>(x, relay_emb);

    for (int l = 0; l < DEPTH; l++) {
        const long rqkv_o = HW_RQKV + (long)l * D_MODEL * 3 * D_MODEL;
        const long row_o  = HW_ROW  + (long)l * D_MODEL * D_MODEL;
        const long lqkv_o = HW_LQKV + (long)l * D_MODEL * 3 * D_MODEL;
        const long low_o  = HW_LOW  + (long)l * D_MODEL * D_MODEL;
        const long fw1_o  = HW_FW1  + (long)l * D_MODEL * DFF;
        const long fw2_o  = HW_FW2  + (long)l * DFF * D_MODEL;

        // ---- relay attention over the 16 relay tokens per batch ----
        ln_kernel<<<32, 256>>>(OFF_XS, HOFF_RLN, r_ln_g + l * D_MODEL, r_ln_b + l * D_MODEL,
                               (long)(GRP + 1) * D_MODEL);
        launch_gemm(8, HOFF_RLN, rqkv_o, nullptr, HOFF_RQKV, 32, 3 * D_MODEL, D_MODEL);
        relay_attn<<<dim3(HEADS, BATCH), 128>>>(HOFF_RQKV, HOFF_RATT);
        launch_gemm(0, HOFF_RATT, row_o, nullptr, OFF_RPRJ, 32, D_MODEL, D_MODEL);
        relay_scatter<<<32, 256>>>(OFF_RPRJ, r_ob + l * D_MODEL);

        // ---- full attention over stitched sequence ----
        ln_kernel<<<MROWS, 256>>>(OFF_XS, HOFF_Y, l_ln_g + l * D_MODEL, l_ln_b + l * D_MODEL,
                                  D_MODEL);
        launch_gemm(8, HOFF_Y, lqkv_o, nullptr, HOFF_QKV, MROWS, 3 * D_MODEL, D_MODEL);
        flash_attn_f16<<<dim3((SEQ + 63) / 64, HEADS, BATCH), 128>>>(HOFF_QKV, HOFF_ATT, SEQ);
        launch_gemm(3, HOFF_ATT, low_o, l_ob + l * D_MODEL, OFF_XS, MROWS, D_MODEL, D_MODEL);

        // ---- FFN ----
        ln_kernel<<<MROWS, 256>>>(OFF_XS, HOFF_Y, f_ln_g + l * D_MODEL, f_ln_b + l * D_MODEL,
                                  D_MODEL);
        launch_gemm(13, HOFF_Y, fw1_o, f_b1 + l * DFF, HOFF_FFN, MROWS, DFF, D_MODEL);
        launch_gemm(3, HOFF_FFN, fw2_o, f_b2 + l * D_MODEL, OFF_XS, MROWS, D_MODEL, DFF);
    }

    final_out<<<BATCH * TOKENS, 256>>>((float*)d_out);
}